// round 15
// baseline (speedup 1.0000x reference)
#include <cuda_runtime.h>
#include <cuda_bf16.h>
#include <math.h>

#define B_ 64
#define L_ 128
#define E_ 512
#define N_ 512
#define H_ 1024
#define G3 3072
#define KA 1536
#define NBLK 296
#define NTHR 256
#define GSZ 74           /* CTAs per group */
#define BG 16            /* batch per group */

#define S1 4             /* gx-h / gh splits (Kc=256) */
#define SQ 4             /* q splits (Kc=256) */
#define SF 4             /* final rnn splits (Kc=256) */

#define P0_UNITS (8192 + 3072)

// ---------------- device scratch (static, no allocations) ----------------
__device__ __nv_bfloat16 g_keysb[(size_t)B_ * N_ * H_];  // 67 MB
__device__ __nv_bfloat16 g_vw[(size_t)B_ * N_ * H_];     // 67 MB: value @ Wm_ctx^T
__device__ float g_gxe[(size_t)B_ * L_ * G3];            // 100 MB
__device__ float g_h[B_ * H_];
__device__ float g_xf[B_ * H_];
__device__ float g_score[B_ * N_];
__device__ float g_attn[B_ * N_];
__device__ float g_gxp[(size_t)S1 * B_ * G3];
__device__ float g_ghp[(size_t)S1 * B_ * G3];
__device__ float g_qp[(size_t)SQ * B_ * H_];
__device__ float g_fp[(size_t)SF * B_ * H_];
// monotone sync state (reset by last CTA at end of each launch)
__device__ unsigned g_q0, c_p0, c_end;
__device__ unsigned g_grp0[37 * 16];      // phase-0 hierarchical arrivals
__device__ unsigned g_garr[4 * 32];       // per-group barrier arrivals
__device__ unsigned g_ggen[4 * 32];       // per-group barrier generation
__device__ unsigned g_gq[12 * 32];        // per-group queues [grp*3+q]
__device__ unsigned g_bc[B_];             // score-quarter parity (mod 4)

__device__ __forceinline__ float tanh_fast(float x) {
    float y;
    asm("tanh.approx.f32 %0, %1;" : "=f"(y) : "f"(x));
    return y;
}

// per-group barrier (74 CTAs); winner optionally resets one group queue
__device__ __forceinline__ void gbar_g(int grp, unsigned& tgt, int resetq) {
    __syncthreads();
    if (threadIdx.x == 0) {
        __threadfence();
        unsigned v = atomicAdd(&g_garr[grp * 32], 1u);
        if (v % (unsigned)GSZ == (unsigned)GSZ - 1u) {
            if (resetq >= 0) atomicExch(&g_gq[(grp * 3 + resetq) * 32], 0u);
            __threadfence();
            atomicAdd(&g_ggen[grp * 32], 1u);
        }
        while ((int)(*(volatile unsigned*)&g_ggen[grp * 32] - tgt) < 0) __nanosleep(32);
        tgt++;
    }
    __syncthreads();
}

__device__ __forceinline__ int qfetch_g(int grp, int q, int* s_u) {
    __syncthreads();
    if (threadIdx.x == 0) *s_u = (int)atomicAdd(&g_gq[(grp * 3 + q) * 32], 1u);
    __syncthreads();
    return *s_u;
}

// ---------------- bf16 split helpers ----------------
__device__ __forceinline__ void split2(float2 v, unsigned& hi, unsigned& lo) {
    __nv_bfloat16 hx = __float2bfloat16_rn(v.x);
    __nv_bfloat16 hy = __float2bfloat16_rn(v.y);
    float rx = v.x - __bfloat162float(hx);
    float ry = v.y - __bfloat162float(hy);
    __nv_bfloat162 h2; h2.x = hx; h2.y = hy;
    __nv_bfloat162 l2 = __floats2bfloat162_rn(rx, ry);
    hi = *(unsigned*)&h2;
    lo = *(unsigned*)&l2;
}

#define MMA16816(c0,c1,c2,c3,a0,a1,a2,a3,b0,b1) \
    asm volatile("mma.sync.aligned.m16n8k16.row.col.f32.bf16.bf16.f32 " \
        "{%0,%1,%2,%3},{%4,%5,%6,%7},{%8,%9},{%0,%1,%2,%3};" \
        : "+f"(c0),"+f"(c1),"+f"(c2),"+f"(c3) \
        : "r"(a0),"r"(a1),"r"(a2),"r"(a3),"r"(b0),"r"(b1))

// ---------------- 64(M) x 128(N) x Kc tile (phase 0 only; proven) -------------
__device__ __forceinline__ void gemm64(
    const float* __restrict__ Ap, int lda,
    const float* __restrict__ Wp, int ldw,
    void* Co, int ldc, int Kc, int bf16out, float* smf)
{
    unsigned* smu = (unsigned*)smf;
    const int tid = threadIdx.x;
    const int lane = tid & 31;
    const int wid = tid >> 5;
    const int g = lane >> 2, tg = lane & 3;
    const int wm = (wid & 3) << 4;
    const int wn = (wid >> 2) << 6;
    const int nkt = Kc >> 4;

    float acc[8][4] = {};
    float2 apf[2], wpf0[2], wpf1[2];
#pragma unroll
    for (int r2 = 0; r2 < 2; r2++) {
        int vt = tid + (r2 << 8);
        int arow = vt >> 3, akp = vt & 7;
        apf[r2]  = __ldcg((const float2*)(Ap + (size_t)arow * lda + 2 * akp));
        wpf0[r2] = *(const float2*)(Wp + (size_t)arow * ldw + 2 * akp);
        wpf1[r2] = *(const float2*)(Wp + (size_t)(arow + 64) * ldw + 2 * akp);
    }
    __syncthreads();
    for (int kt = 0; kt < nkt; kt++) {
        unsigned* buf = smu + (kt & 1) * 4608;
#pragma unroll
        for (int r2 = 0; r2 < 2; r2++) {
            int vt = tid + (r2 << 8);
            int arow = vt >> 3, akp = vt & 7;
            unsigned hi, lo;
            split2(apf[r2], hi, lo);
            buf[arow * 12 + akp] = hi;
            buf[768 + arow * 12 + akp] = lo;
            split2(wpf0[r2], hi, lo);
            buf[1536 + arow * 12 + akp] = hi;
            buf[3072 + arow * 12 + akp] = lo;
            split2(wpf1[r2], hi, lo);
            buf[1536 + (arow + 64) * 12 + akp] = hi;
            buf[3072 + (arow + 64) * 12 + akp] = lo;
        }
        if (kt + 1 < nkt) {
            const float* A2 = Ap + (kt + 1) * 16;
            const float* W2 = Wp + (kt + 1) * 16;
#pragma unroll
            for (int r2 = 0; r2 < 2; r2++) {
                int vt = tid + (r2 << 8);
                int arow = vt >> 3, akp = vt & 7;
                apf[r2]  = __ldcg((const float2*)(A2 + (size_t)arow * lda + 2 * akp));
                wpf0[r2] = *(const float2*)(W2 + (size_t)arow * ldw + 2 * akp);
                wpf1[r2] = *(const float2*)(W2 + (size_t)(arow + 64) * ldw + 2 * akp);
            }
        }
        __syncthreads();
        unsigned a0h = buf[(wm + g) * 12 + tg];
        unsigned a1h = buf[(wm + g + 8) * 12 + tg];
        unsigned a2h = buf[(wm + g) * 12 + tg + 4];
        unsigned a3h = buf[(wm + g + 8) * 12 + tg + 4];
        unsigned a0l = buf[768 + (wm + g) * 12 + tg];
        unsigned a1l = buf[768 + (wm + g + 8) * 12 + tg];
        unsigned a2l = buf[768 + (wm + g) * 12 + tg + 4];
        unsigned a3l = buf[768 + (wm + g + 8) * 12 + tg + 4];
#pragma unroll
        for (int blk = 0; blk < 8; blk++) {
            int r = (wn + blk * 8 + g) * 12;
            unsigned b0h = buf[1536 + r + tg];
            unsigned b1h = buf[1536 + r + tg + 4];
            unsigned b0l = buf[3072 + r + tg];
            unsigned b1l = buf[3072 + r + tg + 4];
            MMA16816(acc[blk][0], acc[blk][1], acc[blk][2], acc[blk][3],
                     a0h, a1h, a2h, a3h, b0h, b1h);
            MMA16816(acc[blk][0], acc[blk][1], acc[blk][2], acc[blk][3],
                     a0h, a1h, a2h, a3h, b0l, b1l);
            MMA16816(acc[blk][0], acc[blk][1], acc[blk][2], acc[blk][3],
                     a0l, a1l, a2l, a3l, b0h, b1h);
        }
    }
    if (!bf16out) {
        float* C = (float*)Co;
#pragma unroll
        for (int blk = 0; blk < 8; blk++) {
            int col = wn + blk * 8 + 2 * tg;
            *(float2*)(C + (size_t)(wm + g) * ldc + col) =
                make_float2(acc[blk][0], acc[blk][1]);
            *(float2*)(C + (size_t)(wm + g + 8) * ldc + col) =
                make_float2(acc[blk][2], acc[blk][3]);
        }
    } else {
        __nv_bfloat16* C = (__nv_bfloat16*)Co;
#pragma unroll
        for (int blk = 0; blk < 8; blk++) {
            int col = wn + blk * 8 + 2 * tg;
            *(__nv_bfloat162*)(C + (size_t)(wm + g) * ldc + col) =
                __floats2bfloat162_rn(acc[blk][0], acc[blk][1]);
            *(__nv_bfloat162*)(C + (size_t)(wm + g + 8) * ldc + col) =
                __floats2bfloat162_rn(acc[blk][2], acc[blk][3]);
        }
    }
}

// ---------------- 16(M) x 128(N) x Kc tile (group GEMMs) ----------------------
// smem per parity (words): [Ah 16x12][Al 16x12][Wh 128x12][Wl 128x12] = 3456
__device__ __forceinline__ void gemm16(
    const float* __restrict__ Ap, int lda,
    const float* __restrict__ Wp, int ldw,
    float* __restrict__ Co, int ldc, int Kc, float* smf)
{
    unsigned* smu = (unsigned*)smf;
    const int tid = threadIdx.x;
    const int lane = tid & 31;
    const int wid = tid >> 5;              // 0..7 -> n block of 16
    const int g = lane >> 2, tg = lane & 3;
    const int nkt = Kc >> 4;

    float acc[2][4] = {};

    float2 awf = make_float2(0.f, 0.f);
    if (tid < 128) awf = __ldcg((const float2*)(Ap + (size_t)(tid >> 3) * lda + 2 * (tid & 7)));
    float2 wwf[4];
#pragma unroll
    for (int r2 = 0; r2 < 4; r2++) {
        int idx = tid + (r2 << 8);
        int row = idx >> 3, c2 = idx & 7;
        wwf[r2] = *(const float2*)(Wp + (size_t)row * ldw + 2 * c2);
    }

    __syncthreads();
    for (int kt = 0; kt < nkt; kt++) {
        unsigned* buf = smu + (kt & 1) * 3456;
        unsigned hi, lo;
        if (tid < 128) {
            int row = tid >> 3, c2 = tid & 7;
            split2(awf, hi, lo);
            buf[row * 12 + c2] = hi;
            buf[192 + row * 12 + c2] = lo;
        }
#pragma unroll
        for (int r2 = 0; r2 < 4; r2++) {
            int idx = tid + (r2 << 8);
            int row = idx >> 3, c2 = idx & 7;
            split2(wwf[r2], hi, lo);
            buf[384 + row * 12 + c2] = hi;
            buf[1920 + row * 12 + c2] = lo;
        }
        if (kt + 1 < nkt) {
            const float* A2 = Ap + (kt + 1) * 16;
            const float* W2 = Wp + (kt + 1) * 16;
            if (tid < 128)
                awf = __ldcg((const float2*)(A2 + (size_t)(tid >> 3) * lda + 2 * (tid & 7)));
#pragma unroll
            for (int r2 = 0; r2 < 4; r2++) {
                int idx = tid + (r2 << 8);
                int row = idx >> 3, c2 = idx & 7;
                wwf[r2] = *(const float2*)(W2 + (size_t)row * ldw + 2 * c2);
            }
        }
        __syncthreads();
        unsigned a0h = buf[g * 12 + tg];
        unsigned a1h = buf[(g + 8) * 12 + tg];
        unsigned a2h = buf[g * 12 + tg + 4];
        unsigned a3h = buf[(g + 8) * 12 + tg + 4];
        unsigned a0l = buf[192 + g * 12 + tg];
        unsigned a1l = buf[192 + (g + 8) * 12 + tg];
        unsigned a2l = buf[192 + g * 12 + tg + 4];
        unsigned a3l = buf[192 + (g + 8) * 12 + tg + 4];
#pragma unroll
        for (int blk = 0; blk < 2; blk++) {
            int r = 384 + ((wid << 4) + blk * 8 + g) * 12;
            unsigned b0h = buf[r + tg];
            unsigned b1h = buf[r + tg + 4];
            unsigned b0l = buf[1536 + r + tg];
            unsigned b1l = buf[1536 + r + tg + 4];
            MMA16816(acc[blk][0], acc[blk][1], acc[blk][2], acc[blk][3],
                     a0h, a1h, a2h, a3h, b0h, b1h);
            MMA16816(acc[blk][0], acc[blk][1], acc[blk][2], acc[blk][3],
                     a0h, a1h, a2h, a3h, b0l, b1l);
            MMA16816(acc[blk][0], acc[blk][1], acc[blk][2], acc[blk][3],
                     a0l, a1l, a2l, a3l, b0h, b1h);
        }
    }
#pragma unroll
    for (int blk = 0; blk < 2; blk++) {
        int col = (wid << 4) + blk * 8 + 2 * tg;
        *(float2*)(Co + (size_t)g * ldc + col) = make_float2(acc[blk][0], acc[blk][1]);
        *(float2*)(Co + (size_t)(g + 8) * ldc + col) = make_float2(acc[blk][2], acc[blk][3]);
    }
}

// ---------------- the one persistent kernel ----------------
__global__ __launch_bounds__(NTHR, 2) void decoder_all(
    const float* __restrict__ emb,   const float* __restrict__ value,
    const float* __restrict__ vmask, const float* __restrict__ state,
    const float* __restrict__ W_ih,  const float* __restrict__ b_ih,
    const float* __restrict__ W_hh,  const float* __restrict__ b_hh,
    const float* __restrict__ Wq,    const float* __restrict__ Wk,
    const float* __restrict__ v_att, const float* __restrict__ Wm,
    const float* __restrict__ bm,
    float* __restrict__ out, float* __restrict__ attn_out)
{
    __shared__ float sm[9216];
    __shared__ float red[16];
    __shared__ int   s_u;
    __shared__ int   s_flag;
    const int bid = blockIdx.x, tid = threadIdx.x;
    const int grp = bid / GSZ;
    const int r   = bid - grp * GSZ;
    const int Bg  = grp * BG;

    unsigned tgt = 0;
    if (tid == 0) tgt = *(volatile unsigned*)&g_ggen[grp * 32] + 1u;
    __syncthreads();

    // ===== phase 0 (global): init h; keys + VW + gxe GEMMs =====
    {
        int i = bid * NTHR + tid;
        if (i < B_ * H_) g_h[i] = state[i];
    }
    for (;;) {
        __syncthreads();
        if (tid == 0) s_u = (int)atomicAdd(&g_q0, 1u);
        __syncthreads();
        int u = s_u;
        if (u >= P0_UNITS) break;
        if (u < 8192) {
            int mt = u >> 4, sub = u & 15;
            if (sub < 8) {
                gemm64(value + (size_t)mt * 64 * H_, H_,
                       Wk + (size_t)sub * 128 * H_, H_,
                       g_keysb + (size_t)mt * 64 * H_ + sub * 128, H_, H_, 1, sm);
            } else {
                int nt = sub - 8;
                gemm64(value + (size_t)mt * 64 * H_, H_,
                       Wm + (size_t)nt * 128 * 2 * H_ + H_, 2 * H_,
                       g_vw + (size_t)mt * 64 * H_ + nt * 128, H_, H_, 1, sm);
            }
        } else {
            int u2 = u - 8192;
            int mt = u2 / 24, nt = u2 % 24;
            gemm64(emb + (size_t)mt * 64 * E_, E_,
                   W_ih + (size_t)nt * 128 * KA, KA,
                   g_gxe + (size_t)mt * 64 * G3 + nt * 128, G3, E_, 0, sm);
        }
    }
    __syncthreads();
    if (tid == 0) {
        __threadfence();
        unsigned v = atomicAdd(&g_grp0[(bid >> 3) * 16], 1u);
        if ((v & 7u) == 7u) atomicAdd(&c_p0, 1u);
        while ((int)(*(volatile unsigned*)&c_p0 - 37u) < 0) __nanosleep(64);
    }
    __syncthreads();

    // ===== per-group independent step loop =====
    for (int t = 0; t < L_; t++) {
        // ---- P1: gx-h (96) + gh (96), M=16, Kc=256, queue 0 ----
        for (;;) {
            int u = qfetch_g(grp, 0, &s_u);
            if (u >= 192) break;
            if (u < 96) {
                int nt = u % 24, s = u / 24;
                gemm16(g_h + Bg * H_ + s * 256, H_,
                       W_ih + (size_t)nt * 128 * KA + E_ + s * 256, KA,
                       g_gxp + ((size_t)s * B_ + Bg) * G3 + nt * 128, G3, 256, sm);
            } else {
                int u2 = u - 96;
                int nt = u2 % 24, s = u2 / 24;
                gemm16(g_h + Bg * H_ + s * 256, H_,
                       W_hh + (size_t)nt * 128 * H_ + s * 256, H_,
                       g_ghp + ((size_t)s * B_ + Bg) * G3 + nt * 128, G3, 256, sm);
            }
        }
        gbar_g(grp, tgt, 0);

        // ---- GRU elementwise (16K elems over 74 CTAs) ----
        {
            int i = r * NTHR + tid;
            if (i < BG * H_) {
                int b = Bg + (i >> 10), j = i & 1023;
                const float* ge = &g_gxe[(size_t)(b * L_ + t) * G3];
                float gxr = ge[j], gxz = ge[H_ + j], gxn = ge[2 * H_ + j];
                float ghr = 0.f, ghz = 0.f, ghn = 0.f;
#pragma unroll
                for (int s = 0; s < S1; s++) {
                    const float* p = &g_gxp[((size_t)s * B_ + b) * G3];
                    gxr += __ldcg(p + j); gxz += __ldcg(p + H_ + j); gxn += __ldcg(p + 2 * H_ + j);
                }
#pragma unroll
                for (int s = 0; s < S1; s++) {
                    const float* p = &g_ghp[((size_t)s * B_ + b) * G3];
                    ghr += __ldcg(p + j); ghz += __ldcg(p + H_ + j); ghn += __ldcg(p + 2 * H_ + j);
                }
                float rr = 1.f / (1.f + expf(-(gxr + b_ih[j]        + ghr + b_hh[j])));
                float z  = 1.f / (1.f + expf(-(gxz + b_ih[H_ + j]   + ghz + b_hh[H_ + j])));
                float n  = tanhf(gxn + b_ih[2 * H_ + j] + rr * (ghn + b_hh[2 * H_ + j]));
                float h  = __ldcg(&g_h[b * H_ + j]);
                g_xf[b * H_ + j] = (1.f - z) * n + z * h;
            }
        }
        gbar_g(grp, tgt, -1);

        // ---- QF: q tiles (32) + final-rnn tiles (32), Kc=256, queue 1 ----
        for (;;) {
            int u = qfetch_g(grp, 1, &s_u);
            if (u >= 64) break;
            if (u < 32) {
                int s = u >> 3, nt = u & 7;
                gemm16(g_xf + Bg * H_ + s * 256, H_,
                       Wq + (size_t)nt * 128 * H_ + s * 256, H_,
                       g_qp + ((size_t)s * B_ + Bg) * H_ + nt * 128, H_, 256, sm);
            } else {
                int u2 = u - 32;
                int s = u2 >> 3, nt = u2 & 7;
                gemm16(g_xf + Bg * H_ + s * 256, H_,
                       Wm + (size_t)nt * 128 * 2 * H_ + s * 256, 2 * H_,
                       g_fp + ((size_t)s * B_ + Bg) * H_ + nt * 128, H_, 256, sm);
            }
        }
        gbar_g(grp, tgt, 1);

        // ---- SCORE: 64 units (16 b x 4 quarters); 4th finisher does softmax ----
        for (;;) {
            int u = qfetch_g(grp, 2, &s_u);
            if (u >= 64) break;
            int b = Bg + (u >> 2), qtr = u & 3;
            for (int j = tid; j < H_; j += NTHR) {
                float a = 0.f;
#pragma unroll
                for (int s = 0; s < SQ; s++)
                    a += __ldcg(&g_qp[((size_t)s * B_ + b) * H_ + j]);
                sm[j] = a;
                sm[H_ + j] = v_att[j];
            }
            __syncthreads();
            int w = tid >> 5, lane = tid & 31;
            for (int i = 0; i < 16; i++) {
                int n = qtr * 128 + w * 16 + i;
                const uint4* kp = (const uint4*)(g_keysb + (size_t)(b * N_ + n) * H_);
                float acc = 0.f;
#pragma unroll
                for (int j2 = 0; j2 < 4; j2++) {
                    uint4 kv = kp[lane + 32 * j2];
                    int c8 = (lane + 32 * j2) << 3;
                    float4 q0 = *(const float4*)(sm + c8);
                    float4 q1 = *(const float4*)(sm + c8 + 4);
                    float4 v0 = *(const float4*)(sm + H_ + c8);
                    float4 v1 = *(const float4*)(sm + H_ + c8 + 4);
                    acc += v0.x * tanh_fast(q0.x + __uint_as_float(kv.x << 16));
                    acc += v0.y * tanh_fast(q0.y + __uint_as_float(kv.x & 0xFFFF0000u));
                    acc += v0.z * tanh_fast(q0.z + __uint_as_float(kv.y << 16));
                    acc += v0.w * tanh_fast(q0.w + __uint_as_float(kv.y & 0xFFFF0000u));
                    acc += v1.x * tanh_fast(q1.x + __uint_as_float(kv.z << 16));
                    acc += v1.y * tanh_fast(q1.y + __uint_as_float(kv.z & 0xFFFF0000u));
                    acc += v1.z * tanh_fast(q1.z + __uint_as_float(kv.w << 16));
                    acc += v1.w * tanh_fast(q1.w + __uint_as_float(kv.w & 0xFFFF0000u));
                }
#pragma unroll
                for (int o = 16; o; o >>= 1) acc += __shfl_xor_sync(0xffffffffu, acc, o);
                if (lane == 0) {
                    float mk = vmask[b * N_ + n];
                    g_score[b * N_ + n] = (mk > 0.f) ? acc : -1e9f;
                }
            }
            __syncthreads();
            if (tid == 0) {
                __threadfence();
                unsigned old = atomicAdd(&g_bc[b], 1u);
                s_flag = ((old & 3u) == 3u) ? 1 : 0;
            }
            __syncthreads();
            if (s_flag) {
                __threadfence();
                float s0 = __ldcg(&g_score[b * N_ + tid]);
                float s1 = __ldcg(&g_score[b * N_ + 256 + tid]);
                float m = fmaxf(s0, s1);
#pragma unroll
                for (int o = 16; o; o >>= 1) m = fmaxf(m, __shfl_xor_sync(0xffffffffu, m, o));
                if (lane == 0) red[w] = m;
                __syncthreads();
                float M = red[0];
#pragma unroll
                for (int i2 = 1; i2 < 8; i2++) M = fmaxf(M, red[i2]);
                float p0 = expf(s0 - M), p1 = expf(s1 - M);
                float ss = p0 + p1;
#pragma unroll
                for (int o = 16; o; o >>= 1) ss += __shfl_xor_sync(0xffffffffu, ss, o);
                if (lane == 0) red[8 + w] = ss;
                __syncthreads();
                float Z = red[8];
#pragma unroll
                for (int i2 = 1; i2 < 8; i2++) Z += red[8 + i2];
                float inv = 1.f / Z;
                float a0 = p0 * inv, a1 = p1 * inv;
                g_attn[b * N_ + tid] = a0;
                g_attn[b * N_ + 256 + tid] = a1;
                attn_out[((size_t)b * L_ + t) * N_ + tid] = a0;
                attn_out[((size_t)b * L_ + t) * N_ + 256 + tid] = a1;
            }
        }
        gbar_g(grp, tgt, 2);

        // ---- P8: fused ctx-from-VW + final sum + tanh; 32 (b, half) units ----
        if (r < 32) {
            int b = Bg + (r >> 1), half = r & 1;
            sm[tid] = __ldcg(&g_attn[b * N_ + tid]);
            sm[256 + tid] = __ldcg(&g_attn[b * N_ + 256 + tid]);
            __syncthreads();
            int pair = half * 256 + tid;
            const __nv_bfloat162* vp =
                (const __nv_bfloat162*)(g_vw + (size_t)b * N_ * H_) + pair;
            float a0 = 0.f, a1 = 0.f;
#pragma unroll 8
            for (int n = 0; n < N_; n++) {
                float2 f = __bfloat1622float2(vp[(size_t)n * (H_ / 2)]);
                float wv = sm[n];
                a0 += wv * f.x;
                a1 += wv * f.y;
            }
            int h0 = 2 * pair;
            float v0 = bm[h0] + a0;
            float v1 = bm[h0 + 1] + a1;
#pragma unroll
            for (int s = 0; s < SF; s++) {
                float2 fp2 = __ldcg((const float2*)&g_fp[((size_t)s * B_ + b) * H_ + h0]);
                v0 += fp2.x;
                v1 += fp2.y;
            }
            float y0 = tanhf(v0), y1 = tanhf(v1);
            *(float2*)&out[((size_t)b * L_ + t) * H_ + h0] = make_float2(y0, y1);
            *(float2*)&g_h[b * H_ + h0] = make_float2(y0, y1);
        }
        gbar_g(grp, tgt, -1);
    }

    // ---- end: last CTA resets all monotone state for next graph replay ----
    __syncthreads();
    if (tid == 0) {
        __threadfence();
        unsigned old = atomicAdd(&c_end, 1u);
        if (old == NBLK - 1u) {
            g_q0 = 0; c_p0 = 0;
            for (int i = 0; i < 37 * 16; i++) g_grp0[i] = 0;
            for (int i = 0; i < 4 * 32; i++) { g_garr[i] = 0; g_ggen[i] = 0; }
            for (int i = 0; i < 12 * 32; i++) g_gq[i] = 0;
            for (int b = 0; b < B_; b++) g_bc[b] = 0;
            __threadfence();
            atomicExch(&c_end, 0u);
        }
    }
}

// ---------------- launch: ONE graph node ----------------
extern "C" void kernel_launch(void* const* d_in, const int* in_sizes, int n_in,
                              void* d_out, int out_size) {
    const float* emb    = (const float*)d_in[0];
    const float* value  = (const float*)d_in[1];
    const float* vmask  = (const float*)d_in[2];
    const float* state  = (const float*)d_in[3];
    const float* W_ih   = (const float*)d_in[4];
    const float* b_ih   = (const float*)d_in[5];
    const float* W_hh   = (const float*)d_in[6];
    const float* b_hh   = (const float*)d_in[7];
    const float* Wq     = (const float*)d_in[8];
    const float* Wk     = (const float*)d_in[9];
    const float* v_att  = (const float*)d_in[10];
    const float* Wm     = (const float*)d_in[11];
    const float* bm     = (const float*)d_in[12];

    float* out      = (float*)d_out;                 // outputs: B x L x H
    float* attn_out = out + (size_t)B_ * L_ * H_;    // attns:   B x L x N

    decoder_all<<<NBLK, NTHR>>>(emb, value, vmask, state, W_ih, b_ih, W_hh, b_hh,
                                Wq, Wk, v_att, Wm, bm, out, attn_out);
}

// round 16
// speedup vs baseline: 1.3069x; 1.3069x over previous
#include <cuda_runtime.h>
#include <cuda_bf16.h>
#include <math.h>

#define B_ 64
#define L_ 128
#define E_ 512
#define N_ 512
#define H_ 1024
#define G3 3072
#define KA 1536
#define NBLK 296
#define NTHR 256

#define S1 8             /* gx-h / gh splits (Kc=128) */
#define SQ 8             /* q splits (Kc=128) */
#define SF 8             /* final rnn splits (Kc=128) */

#define P0_UNITS (8192 + 3072)

// ---------------- device scratch (static, no allocations) ----------------
__device__ __nv_bfloat16 g_keysb[(size_t)B_ * N_ * H_];  // 67 MB
__device__ __nv_bfloat16 g_vw[(size_t)B_ * N_ * H_];     // 67 MB: value @ Wm_ctx^T
__device__ float g_gxe[(size_t)B_ * L_ * G3];            // 100 MB
__device__ float g_h[B_ * H_];
__device__ float g_xf[B_ * H_];
__device__ float g_score[B_ * N_];
__device__ float g_attn[B_ * N_];
__device__ float g_gxp[(size_t)S1 * B_ * G3];
__device__ float g_ghp[(size_t)S1 * B_ * G3];
__device__ float g_qp[(size_t)SQ * B_ * H_];
__device__ float g_fp[(size_t)SF * B_ * H_];
// monotone sync state (reset by last CTA at end of each launch)
__device__ unsigned g_grp[5 * 37 * 32];   // hierarchical group counters, 128B apart
__device__ unsigned c_p1, c_gru, c_qf, c_sc, c_p8, c_end;
__device__ unsigned g_bc[B_];             // score-quarter parity (mod 4)

__device__ __forceinline__ float tanh_fast(float x) {
    float y;
    asm("tanh.approx.f32 %0, %1;" : "=f"(y) : "f"(x));
    return y;
}

// full hierarchical barrier: arrive (group -> root) then poll root
__device__ __forceinline__ void phase_gate(int ph, unsigned* root, unsigned tgt) {
    __syncthreads();
    if (threadIdx.x == 0) {
        __threadfence();
        unsigned v = atomicAdd(&g_grp[(ph * 37 + ((int)blockIdx.x >> 3)) * 32], 1u);
        if ((v & 7u) == 7u) atomicAdd(root, 1u);
        while ((int)(*(volatile unsigned*)root - tgt) < 0) __nanosleep(32);
    }
    __syncthreads();
}

// ---------------- bf16 split helpers ----------------
__device__ __forceinline__ void split2(float2 v, unsigned& hi, unsigned& lo) {
    __nv_bfloat16 hx = __float2bfloat16_rn(v.x);
    __nv_bfloat16 hy = __float2bfloat16_rn(v.y);
    float rx = v.x - __bfloat162float(hx);
    float ry = v.y - __bfloat162float(hy);
    __nv_bfloat162 h2; h2.x = hx; h2.y = hy;
    __nv_bfloat162 l2 = __floats2bfloat162_rn(rx, ry);
    hi = *(unsigned*)&h2;
    lo = *(unsigned*)&l2;
}

#define MMA16816(c0,c1,c2,c3,a0,a1,a2,a3,b0,b1) \
    asm volatile("mma.sync.aligned.m16n8k16.row.col.f32.bf16.bf16.f32 " \
        "{%0,%1,%2,%3},{%4,%5,%6,%7},{%8,%9},{%0,%1,%2,%3};" \
        : "+f"(c0),"+f"(c1),"+f"(c2),"+f"(c3) \
        : "r"(a0),"r"(a1),"r"(a2),"r"(a3),"r"(b0),"r"(b1))

// ---------------- 64(M) x 128(N) x Kc GEMM tile, split-bf16 MMA, 256 threads --
__device__ __forceinline__ void gemm_mma(
    const float* __restrict__ Ap, int lda,
    const float* __restrict__ Wp, int ldw,
    void* Co, int ldc, int Kc, int bf16out, float* smf)
{
    unsigned* smu = (unsigned*)smf;
    const int tid = threadIdx.x;
    const int lane = tid & 31;
    const int wid = tid >> 5;
    const int g = lane >> 2, tg = lane & 3;
    const int wm = (wid & 3) << 4;
    const int wn = (wid >> 2) << 6;
    const int nkt = Kc >> 4;

    float acc[8][4] = {};

    float2 apf[2], wpf0[2], wpf1[2];
#pragma unroll
    for (int r2 = 0; r2 < 2; r2++) {
        int vt = tid + (r2 << 8);
        int arow = vt >> 3, akp = vt & 7;
        apf[r2]  = __ldcg((const float2*)(Ap + (size_t)arow * lda + 2 * akp));
        wpf0[r2] = *(const float2*)(Wp + (size_t)arow * ldw + 2 * akp);
        wpf1[r2] = *(const float2*)(Wp + (size_t)(arow + 64) * ldw + 2 * akp);
    }

    __syncthreads();
    for (int kt = 0; kt < nkt; kt++) {
        unsigned* buf = smu + (kt & 1) * 4608;
#pragma unroll
        for (int r2 = 0; r2 < 2; r2++) {
            int vt = tid + (r2 << 8);
            int arow = vt >> 3, akp = vt & 7;
            unsigned hi, lo;
            split2(apf[r2], hi, lo);
            buf[arow * 12 + akp] = hi;
            buf[768 + arow * 12 + akp] = lo;
            split2(wpf0[r2], hi, lo);
            buf[1536 + arow * 12 + akp] = hi;
            buf[3072 + arow * 12 + akp] = lo;
            split2(wpf1[r2], hi, lo);
            buf[1536 + (arow + 64) * 12 + akp] = hi;
            buf[3072 + (arow + 64) * 12 + akp] = lo;
        }
        if (kt + 1 < nkt) {
            const float* A2 = Ap + (kt + 1) * 16;
            const float* W2 = Wp + (kt + 1) * 16;
#pragma unroll
            for (int r2 = 0; r2 < 2; r2++) {
                int vt = tid + (r2 << 8);
                int arow = vt >> 3, akp = vt & 7;
                apf[r2]  = __ldcg((const float2*)(A2 + (size_t)arow * lda + 2 * akp));
                wpf0[r2] = *(const float2*)(W2 + (size_t)arow * ldw + 2 * akp);
                wpf1[r2] = *(const float2*)(W2 + (size_t)(arow + 64) * ldw + 2 * akp);
            }
        }
        __syncthreads();
        unsigned a0h = buf[(wm + g) * 12 + tg];
        unsigned a1h = buf[(wm + g + 8) * 12 + tg];
        unsigned a2h = buf[(wm + g) * 12 + tg + 4];
        unsigned a3h = buf[(wm + g + 8) * 12 + tg + 4];
        unsigned a0l = buf[768 + (wm + g) * 12 + tg];
        unsigned a1l = buf[768 + (wm + g + 8) * 12 + tg];
        unsigned a2l = buf[768 + (wm + g) * 12 + tg + 4];
        unsigned a3l = buf[768 + (wm + g + 8) * 12 + tg + 4];
#pragma unroll
        for (int blk = 0; blk < 8; blk++) {
            int r = (wn + blk * 8 + g) * 12;
            unsigned b0h = buf[1536 + r + tg];
            unsigned b1h = buf[1536 + r + tg + 4];
            unsigned b0l = buf[3072 + r + tg];
            unsigned b1l = buf[3072 + r + tg + 4];
            MMA16816(acc[blk][0], acc[blk][1], acc[blk][2], acc[blk][3],
                     a0h, a1h, a2h, a3h, b0h, b1h);
            MMA16816(acc[blk][0], acc[blk][1], acc[blk][2], acc[blk][3],
                     a0h, a1h, a2h, a3h, b0l, b1l);
            MMA16816(acc[blk][0], acc[blk][1], acc[blk][2], acc[blk][3],
                     a0l, a1l, a2l, a3l, b0h, b1h);
        }
    }
    if (!bf16out) {
        float* C = (float*)Co;
#pragma unroll
        for (int blk = 0; blk < 8; blk++) {
            int col = wn + blk * 8 + 2 * tg;
            *(float2*)(C + (size_t)(wm + g) * ldc + col) =
                make_float2(acc[blk][0], acc[blk][1]);
            *(float2*)(C + (size_t)(wm + g + 8) * ldc + col) =
                make_float2(acc[blk][2], acc[blk][3]);
        }
    } else {
        __nv_bfloat16* C = (__nv_bfloat16*)Co;
#pragma unroll
        for (int blk = 0; blk < 8; blk++) {
            int col = wn + blk * 8 + 2 * tg;
            *(__nv_bfloat162*)(C + (size_t)(wm + g) * ldc + col) =
                __floats2bfloat162_rn(acc[blk][0], acc[blk][1]);
            *(__nv_bfloat162*)(C + (size_t)(wm + g + 8) * ldc + col) =
                __floats2bfloat162_rn(acc[blk][2], acc[blk][3]);
        }
    }
}

// ---------------- the one persistent kernel ----------------
__global__ __launch_bounds__(NTHR, 2) void decoder_all(
    const float* __restrict__ emb,   const float* __restrict__ value,
    const float* __restrict__ vmask, const float* __restrict__ state,
    const float* __restrict__ W_ih,  const float* __restrict__ b_ih,
    const float* __restrict__ W_hh,  const float* __restrict__ b_hh,
    const float* __restrict__ Wq,    const float* __restrict__ Wk,
    const float* __restrict__ v_att, const float* __restrict__ Wm,
    const float* __restrict__ bm,
    float* __restrict__ out, float* __restrict__ attn_out)
{
    __shared__ float sm[9216];
    __shared__ float red[16];
    __shared__ int   s_flag;
    const int bid = blockIdx.x, tid = threadIdx.x;

    // ===== phase 0 (static): init h; keys + VW + gxe GEMMs =====
    {
        int i = bid * NTHR + tid;
        if (i < B_ * H_) g_h[i] = state[i];
    }
    for (int u = bid; u < P0_UNITS; u += NBLK) {
        if (u < 8192) {
            int mt = u >> 4, sub = u & 15;
            if (sub < 8) {
                gemm_mma(value + (size_t)mt * 64 * H_, H_,
                         Wk + (size_t)sub * 128 * H_, H_,
                         g_keysb + (size_t)mt * 64 * H_ + sub * 128, H_, H_, 1, sm);
            } else {
                int nt = sub - 8;
                gemm_mma(value + (size_t)mt * 64 * H_, H_,
                         Wm + (size_t)nt * 128 * 2 * H_ + H_, 2 * H_,
                         g_vw + (size_t)mt * 64 * H_ + nt * 128, H_, H_, 1, sm);
            }
        } else {
            int u2 = u - 8192;
            int mt = u2 / 24, nt = u2 % 24;
            gemm_mma(emb + (size_t)mt * 64 * E_, E_,
                     W_ih + (size_t)nt * 128 * KA, KA,
                     g_gxe + (size_t)mt * 64 * G3 + nt * 128, G3, E_, 0, sm);
        }
    }
    phase_gate(4, &c_p8, 37u);   // phase-0 complete (c_p8 stream primed with 37)

    for (int t = 0; t < L_; t++) {
        const unsigned t1 = (unsigned)(t + 1);

        // ---- P1 (static): gx-h (u<192) + gh (u>=192), Kc=128 ----
        for (int u = bid; u < 384; u += NBLK) {
            if (u < 192) {
                int nt = u % 24, s = u / 24;
                gemm_mma(g_h + s * 128, H_,
                         W_ih + (size_t)nt * 128 * KA + E_ + s * 128, KA,
                         g_gxp + (size_t)s * B_ * G3 + nt * 128, G3, 128, 0, sm);
            } else {
                int u2 = u - 192;
                int nt = u2 % 24, s = u2 / 24;
                gemm_mma(g_h + s * 128, H_,
                         W_hh + (size_t)nt * 128 * H_ + s * 128, H_,
                         g_ghp + (size_t)s * B_ * G3 + nt * 128, G3, 128, 0, sm);
            }
        }
        phase_gate(0, &c_p1, 37u * t1);

        // ---- GRU (static, bids 0..255) ----
        {
            int i = bid * NTHR + tid;
            if (i < B_ * H_) {
                int b = i >> 10, j = i & 1023;
                const float* ge = &g_gxe[(size_t)(b * L_ + t) * G3];
                float gxr = ge[j], gxz = ge[H_ + j], gxn = ge[2 * H_ + j];
                float ghr = 0.f, ghz = 0.f, ghn = 0.f;
#pragma unroll
                for (int s = 0; s < S1; s++) {
                    const float* p = &g_gxp[((size_t)s * B_ + b) * G3];
                    gxr += __ldcg(p + j); gxz += __ldcg(p + H_ + j); gxn += __ldcg(p + 2 * H_ + j);
                }
#pragma unroll
                for (int s = 0; s < S1; s++) {
                    const float* p = &g_ghp[((size_t)s * B_ + b) * G3];
                    ghr += __ldcg(p + j); ghz += __ldcg(p + H_ + j); ghn += __ldcg(p + 2 * H_ + j);
                }
                float r = 1.f / (1.f + expf(-(gxr + b_ih[j]        + ghr + b_hh[j])));
                float z = 1.f / (1.f + expf(-(gxz + b_ih[H_ + j]   + ghz + b_hh[H_ + j])));
                float n = tanhf(gxn + b_ih[2 * H_ + j] + r * (ghn + b_hh[2 * H_ + j]));
                float h = __ldcg(&g_h[i]);
                g_xf[i] = (1.f - z) * n + z * h;
            }
        }
        phase_gate(1, &c_gru, 37u * t1);

        // ---- QF (static, bids 0..127): q (u<64) + final-rnn (u>=64), Kc=128 ----
        if (bid < 128) {
            if (bid < 64) {
                int s = bid >> 3, nt = bid & 7;
                gemm_mma(g_xf + s * 128, H_,
                         Wq + (size_t)nt * 128 * H_ + s * 128, H_,
                         g_qp + (size_t)s * B_ * H_ + nt * 128, H_, 128, 0, sm);
            } else {
                int u2 = bid - 64;
                int s = u2 >> 3, nt = u2 & 7;
                gemm_mma(g_xf + s * 128, H_,
                         Wm + (size_t)nt * 128 * 2 * H_ + s * 128, 2 * H_,
                         g_fp + (size_t)s * B_ * H_ + nt * 128, H_, 128, 0, sm);
            }
        }
        phase_gate(2, &c_qf, 37u * t1);

        // ---- SCORE (static, bids 0..255): (b, qtr); 4th finisher does softmax ----
        if (bid < 256) {
            int b = bid >> 2, qtr = bid & 3;
            for (int j = tid; j < H_; j += NTHR) {
                float a = 0.f;
#pragma unroll
                for (int s = 0; s < SQ; s++)
                    a += __ldcg(&g_qp[((size_t)s * B_ + b) * H_ + j]);
                sm[j] = a;
                sm[H_ + j] = v_att[j];
            }
            __syncthreads();
            int w = tid >> 5, lane = tid & 31;
            for (int i = 0; i < 16; i++) {
                int n = qtr * 128 + w * 16 + i;
                const uint4* kp = (const uint4*)(g_keysb + (size_t)(b * N_ + n) * H_);
                float acc = 0.f;
#pragma unroll
                for (int j2 = 0; j2 < 4; j2++) {
                    uint4 kv = kp[lane + 32 * j2];
                    int c8 = (lane + 32 * j2) << 3;
                    float4 q0 = *(const float4*)(sm + c8);
                    float4 q1 = *(const float4*)(sm + c8 + 4);
                    float4 v0 = *(const float4*)(sm + H_ + c8);
                    float4 v1 = *(const float4*)(sm + H_ + c8 + 4);
                    acc += v0.x * tanh_fast(q0.x + __uint_as_float(kv.x << 16));
                    acc += v0.y * tanh_fast(q0.y + __uint_as_float(kv.x & 0xFFFF0000u));
                    acc += v0.z * tanh_fast(q0.z + __uint_as_float(kv.y << 16));
                    acc += v0.w * tanh_fast(q0.w + __uint_as_float(kv.y & 0xFFFF0000u));
                    acc += v1.x * tanh_fast(q1.x + __uint_as_float(kv.z << 16));
                    acc += v1.y * tanh_fast(q1.y + __uint_as_float(kv.z & 0xFFFF0000u));
                    acc += v1.z * tanh_fast(q1.z + __uint_as_float(kv.w << 16));
                    acc += v1.w * tanh_fast(q1.w + __uint_as_float(kv.w & 0xFFFF0000u));
                }
#pragma unroll
                for (int o = 16; o; o >>= 1) acc += __shfl_xor_sync(0xffffffffu, acc, o);
                if (lane == 0) {
                    float mk = vmask[b * N_ + n];
                    g_score[b * N_ + n] = (mk > 0.f) ? acc : -1e9f;
                }
            }
            __syncthreads();
            if (tid == 0) {
                __threadfence();
                unsigned old = atomicAdd(&g_bc[b], 1u);
                s_flag = ((old & 3u) == 3u) ? 1 : 0;
            }
            __syncthreads();
            if (s_flag) {
                __threadfence();
                float s0 = __ldcg(&g_score[b * N_ + tid]);
                float s1 = __ldcg(&g_score[b * N_ + 256 + tid]);
                float m = fmaxf(s0, s1);
#pragma unroll
                for (int o = 16; o; o >>= 1) m = fmaxf(m, __shfl_xor_sync(0xffffffffu, m, o));
                if (lane == 0) red[w] = m;
                __syncthreads();
                float M = red[0];
#pragma unroll
                for (int i2 = 1; i2 < 8; i2++) M = fmaxf(M, red[i2]);
                float p0 = expf(s0 - M), p1 = expf(s1 - M);
                float ss = p0 + p1;
#pragma unroll
                for (int o = 16; o; o >>= 1) ss += __shfl_xor_sync(0xffffffffu, ss, o);
                if (lane == 0) red[8 + w] = ss;
                __syncthreads();
                float Z = red[8];
#pragma unroll
                for (int i2 = 1; i2 < 8; i2++) Z += red[8 + i2];
                float inv = 1.f / Z;
                float a0 = p0 * inv, a1 = p1 * inv;
                g_attn[b * N_ + tid] = a0;
                g_attn[b * N_ + 256 + tid] = a1;
                attn_out[((size_t)b * L_ + t) * N_ + tid] = a0;
                attn_out[((size_t)b * L_ + t) * N_ + 256 + tid] = a1;
            }
        }
        phase_gate(3, &c_sc, 37u * t1);

        // ---- P8 (static, bids 0..255): (b, qtr-H) fused fc + final sum + tanh ----
        if (bid < 256) {
            int b = bid >> 2, qtr = bid & 3;
            sm[tid] = __ldcg(&g_attn[b * N_ + tid]);
            sm[256 + tid] = __ldcg(&g_attn[b * N_ + 256 + tid]);
            __syncthreads();
            // thread: pair pp in quarter, n-half nh; accumulate over 256 rows
            int nh = tid >> 7, pp = tid & 127;
            int pair = qtr * 128 + pp;
            const __nv_bfloat162* vp =
                (const __nv_bfloat162*)(g_vw + (size_t)b * N_ * H_) + pair;
            const float* aw = sm + nh * 256;
            vp += (size_t)(nh * 256) * (H_ / 2);
            float a0 = 0.f, a1 = 0.f;
#pragma unroll 8
            for (int n = 0; n < 256; n++) {
                float2 f = __bfloat1622float2(vp[(size_t)n * (H_ / 2)]);
                float wv = aw[n];
                a0 += wv * f.x;
                a1 += wv * f.y;
            }
            sm[512 + 2 * tid]     = a0;
            sm[512 + 2 * tid + 1] = a1;
            __syncthreads();
            if (tid < 128) {
                float f0 = sm[512 + 2 * tid] + sm[512 + 2 * (tid + 128)];
                float f1 = sm[512 + 2 * tid + 1] + sm[512 + 2 * (tid + 128) + 1];
                int h0 = 2 * (qtr * 128 + tid);
                float v0 = bm[h0] + f0;
                float v1 = bm[h0 + 1] + f1;
#pragma unroll
                for (int s = 0; s < SF; s++) {
                    float2 fp2 = __ldcg((const float2*)&g_fp[((size_t)s * B_ + b) * H_ + h0]);
                    v0 += fp2.x;
                    v1 += fp2.y;
                }
                float y0 = tanhf(v0), y1 = tanhf(v1);
                *(float2*)&out[((size_t)b * L_ + t) * H_ + h0] = make_float2(y0, y1);
                *(float2*)&g_h[b * H_ + h0] = make_float2(y0, y1);
            }
        }
        phase_gate(4, &c_p8, 37u * (unsigned)(t + 2));
    }

    // ---- end: last CTA resets all monotone state for next graph replay ----
    __syncthreads();
    if (tid == 0) {
        __threadfence();
        unsigned old = atomicAdd(&c_end, 1u);
        if (old == NBLK - 1u) {
            c_p1 = 0; c_gru = 0; c_qf = 0; c_sc = 0; c_p8 = 0;
            for (int i = 0; i < 5 * 37 * 32; i++) g_grp[i] = 0;
            for (int b = 0; b < B_; b++) g_bc[b] = 0;
            __threadfence();
            atomicExch(&c_end, 0u);
        }
    }
}

// ---------------- launch: ONE graph node ----------------
extern "C" void kernel_launch(void* const* d_in, const int* in_sizes, int n_in,
                              void* d_out, int out_size) {
    const float* emb    = (const float*)d_in[0];
    const float* value  = (const float*)d_in[1];
    const float* vmask  = (const float*)d_in[2];
    const float* state  = (const float*)d_in[3];
    const float* W_ih   = (const float*)d_in[4];
    const float* b_ih   = (const float*)d_in[5];
    const float* W_hh   = (const float*)d_in[6];
    const float* b_hh   = (const float*)d_in[7];
    const float* Wq     = (const float*)d_in[8];
    const float* Wk     = (const float*)d_in[9];
    const float* v_att  = (const float*)d_in[10];
    const float* Wm     = (const float*)d_in[11];
    const float* bm     = (const float*)d_in[12];

    float* out      = (float*)d_out;                 // outputs: B x L x H
    float* attn_out = out + (size_t)B_ * L_ * H_;    // attns:   B x L x N

    decoder_all<<<NBLK, NTHR>>>(emb, value, vmask, state, W_ih, b_ih, W_hh, b_hh,
                                Wq, Wk, v_att, Wm, bm, out, attn_out);
}

// round 17
// speedup vs baseline: 1.4145x; 1.0823x over previous
#include <cuda_runtime.h>
#include <cuda_bf16.h>
#include <math.h>

#define B_ 64
#define L_ 128
#define E_ 512
#define N_ 512
#define H_ 1024
#define G3 3072
#define KA 1536
#define NBLK 296
#define NTHR 256

#define S1 8             /* gx-h / gh splits (Kc=128) */
#define SQ 16            /* q splits (Kc=64) */
#define SF 16            /* final rnn splits (Kc=64) */

#define P0_UNITS (8192 + 3072)

// ---------------- device scratch (static, no allocations) ----------------
__device__ __nv_bfloat16 g_keysb[(size_t)B_ * N_ * H_];  // 67 MB
__device__ __nv_bfloat16 g_vw[(size_t)B_ * N_ * H_];     // 67 MB: value @ Wm_ctx^T
__device__ float g_gxe[(size_t)B_ * L_ * G3];            // 100 MB
__device__ float g_h[B_ * H_];
__device__ float g_xf[B_ * H_];
__device__ float g_score[B_ * N_];
__device__ float g_attn[B_ * N_];
__device__ float g_gxp[(size_t)S1 * B_ * G3];
__device__ float g_ghp[(size_t)S1 * B_ * G3];
__device__ float g_qp[(size_t)SQ * B_ * H_];
__device__ float g_fp[(size_t)SF * B_ * H_];
// monotone sync state (reset by last CTA at end of each launch)
__device__ unsigned g_grp[4 * 37 * 32];   // hierarchical group counters, 128B apart
__device__ unsigned c_p1, c_gru, c_qf, c_p8, c_end;
__device__ unsigned g_bc[B_];             // score-quarter parity (mod 4)
__device__ unsigned g_smb[B_];            // per-b softmax-done counter

__device__ __forceinline__ float tanh_fast(float x) {
    float y;
    asm("tanh.approx.f32 %0, %1;" : "=f"(y) : "f"(x));
    return y;
}

// full hierarchical barrier: arrive (group -> root) then poll root
__device__ __forceinline__ void phase_gate(int ph, unsigned* root, unsigned tgt) {
    __syncthreads();
    if (threadIdx.x == 0) {
        __threadfence();
        unsigned v = atomicAdd(&g_grp[(ph * 37 + ((int)blockIdx.x >> 3)) * 32], 1u);
        if ((v & 7u) == 7u) atomicAdd(root, 1u);
        while ((int)(*(volatile unsigned*)root - tgt) < 0) __nanosleep(32);
    }
    __syncthreads();
}

// ---------------- bf16 split helpers ----------------
__device__ __forceinline__ void split2(float2 v, unsigned& hi, unsigned& lo) {
    __nv_bfloat16 hx = __float2bfloat16_rn(v.x);
    __nv_bfloat16 hy = __float2bfloat16_rn(v.y);
    float rx = v.x - __bfloat162float(hx);
    float ry = v.y - __bfloat162float(hy);
    __nv_bfloat162 h2; h2.x = hx; h2.y = hy;
    __nv_bfloat162 l2 = __floats2bfloat162_rn(rx, ry);
    hi = *(unsigned*)&h2;
    lo = *(unsigned*)&l2;
}

#define MMA16816(c0,c1,c2,c3,a0,a1,a2,a3,b0,b1) \
    asm volatile("mma.sync.aligned.m16n8k16.row.col.f32.bf16.bf16.f32 " \
        "{%0,%1,%2,%3},{%4,%5,%6,%7},{%8,%9},{%0,%1,%2,%3};" \
        : "+f"(c0),"+f"(c1),"+f"(c2),"+f"(c3) \
        : "r"(a0),"r"(a1),"r"(a2),"r"(a3),"r"(b0),"r"(b1))

// ---------------- 64(M) x 128(N) x Kc GEMM tile, split-bf16 MMA, 256 threads --
__device__ __forceinline__ void gemm_mma(
    const float* __restrict__ Ap, int lda,
    const float* __restrict__ Wp, int ldw,
    void* Co, int ldc, int Kc, int bf16out, float* smf)
{
    unsigned* smu = (unsigned*)smf;
    const int tid = threadIdx.x;
    const int lane = tid & 31;
    const int wid = tid >> 5;
    const int g = lane >> 2, tg = lane & 3;
    const int wm = (wid & 3) << 4;
    const int wn = (wid >> 2) << 6;
    const int nkt = Kc >> 4;

    float acc[8][4] = {};

    float2 apf[2], wpf0[2], wpf1[2];
#pragma unroll
    for (int r2 = 0; r2 < 2; r2++) {
        int vt = tid + (r2 << 8);
        int arow = vt >> 3, akp = vt & 7;
        apf[r2]  = __ldcg((const float2*)(Ap + (size_t)arow * lda + 2 * akp));
        wpf0[r2] = *(const float2*)(Wp + (size_t)arow * ldw + 2 * akp);
        wpf1[r2] = *(const float2*)(Wp + (size_t)(arow + 64) * ldw + 2 * akp);
    }

    __syncthreads();
    for (int kt = 0; kt < nkt; kt++) {
        unsigned* buf = smu + (kt & 1) * 4608;
#pragma unroll
        for (int r2 = 0; r2 < 2; r2++) {
            int vt = tid + (r2 << 8);
            int arow = vt >> 3, akp = vt & 7;
            unsigned hi, lo;
            split2(apf[r2], hi, lo);
            buf[arow * 12 + akp] = hi;
            buf[768 + arow * 12 + akp] = lo;
            split2(wpf0[r2], hi, lo);
            buf[1536 + arow * 12 + akp] = hi;
            buf[3072 + arow * 12 + akp] = lo;
            split2(wpf1[r2], hi, lo);
            buf[1536 + (arow + 64) * 12 + akp] = hi;
            buf[3072 + (arow + 64) * 12 + akp] = lo;
        }
        if (kt + 1 < nkt) {
            const float* A2 = Ap + (kt + 1) * 16;
            const float* W2 = Wp + (kt + 1) * 16;
#pragma unroll
            for (int r2 = 0; r2 < 2; r2++) {
                int vt = tid + (r2 << 8);
                int arow = vt >> 3, akp = vt & 7;
                apf[r2]  = __ldcg((const float2*)(A2 + (size_t)arow * lda + 2 * akp));
                wpf0[r2] = *(const float2*)(W2 + (size_t)arow * ldw + 2 * akp);
                wpf1[r2] = *(const float2*)(W2 + (size_t)(arow + 64) * ldw + 2 * akp);
            }
        }
        __syncthreads();
        unsigned a0h = buf[(wm + g) * 12 + tg];
        unsigned a1h = buf[(wm + g + 8) * 12 + tg];
        unsigned a2h = buf[(wm + g) * 12 + tg + 4];
        unsigned a3h = buf[(wm + g + 8) * 12 + tg + 4];
        unsigned a0l = buf[768 + (wm + g) * 12 + tg];
        unsigned a1l = buf[768 + (wm + g + 8) * 12 + tg];
        unsigned a2l = buf[768 + (wm + g) * 12 + tg + 4];
        unsigned a3l = buf[768 + (wm + g + 8) * 12 + tg + 4];
#pragma unroll
        for (int blk = 0; blk < 8; blk++) {
            int r = (wn + blk * 8 + g) * 12;
            unsigned b0h = buf[1536 + r + tg];
            unsigned b1h = buf[1536 + r + tg + 4];
            unsigned b0l = buf[3072 + r + tg];
            unsigned b1l = buf[3072 + r + tg + 4];
            MMA16816(acc[blk][0], acc[blk][1], acc[blk][2], acc[blk][3],
                     a0h, a1h, a2h, a3h, b0h, b1h);
            MMA16816(acc[blk][0], acc[blk][1], acc[blk][2], acc[blk][3],
                     a0h, a1h, a2h, a3h, b0l, b1l);
            MMA16816(acc[blk][0], acc[blk][1], acc[blk][2], acc[blk][3],
                     a0l, a1l, a2l, a3l, b0h, b1h);
        }
    }
    if (!bf16out) {
        float* C = (float*)Co;
#pragma unroll
        for (int blk = 0; blk < 8; blk++) {
            int col = wn + blk * 8 + 2 * tg;
            *(float2*)(C + (size_t)(wm + g) * ldc + col) =
                make_float2(acc[blk][0], acc[blk][1]);
            *(float2*)(C + (size_t)(wm + g + 8) * ldc + col) =
                make_float2(acc[blk][2], acc[blk][3]);
        }
    } else {
        __nv_bfloat16* C = (__nv_bfloat16*)Co;
#pragma unroll
        for (int blk = 0; blk < 8; blk++) {
            int col = wn + blk * 8 + 2 * tg;
            *(__nv_bfloat162*)(C + (size_t)(wm + g) * ldc + col) =
                __floats2bfloat162_rn(acc[blk][0], acc[blk][1]);
            *(__nv_bfloat162*)(C + (size_t)(wm + g + 8) * ldc + col) =
                __floats2bfloat162_rn(acc[blk][2], acc[blk][3]);
        }
    }
}

// ---------------- the one persistent kernel ----------------
__global__ __launch_bounds__(NTHR, 2) void decoder_all(
    const float* __restrict__ emb,   const float* __restrict__ value,
    const float* __restrict__ vmask, const float* __restrict__ state,
    const float* __restrict__ W_ih,  const float* __restrict__ b_ih,
    const float* __restrict__ W_hh,  const float* __restrict__ b_hh,
    const float* __restrict__ Wq,    const float* __restrict__ Wk,
    const float* __restrict__ v_att, const float* __restrict__ Wm,
    const float* __restrict__ bm,
    float* __restrict__ out, float* __restrict__ attn_out)
{
    __shared__ float sm[9216];
    __shared__ float red[16];
    __shared__ int   s_flag;
    const int bid = blockIdx.x, tid = threadIdx.x;

    // ===== phase 0 (static): init h; keys + VW + gxe GEMMs =====
    {
        int i = bid * NTHR + tid;
        if (i < B_ * H_) g_h[i] = state[i];
    }
    for (int u = bid; u < P0_UNITS; u += NBLK) {
        if (u < 8192) {
            int mt = u >> 4, sub = u & 15;
            if (sub < 8) {
                gemm_mma(value + (size_t)mt * 64 * H_, H_,
                         Wk + (size_t)sub * 128 * H_, H_,
                         g_keysb + (size_t)mt * 64 * H_ + sub * 128, H_, H_, 1, sm);
            } else {
                int nt = sub - 8;
                gemm_mma(value + (size_t)mt * 64 * H_, H_,
                         Wm + (size_t)nt * 128 * 2 * H_ + H_, 2 * H_,
                         g_vw + (size_t)mt * 64 * H_ + nt * 128, H_, H_, 1, sm);
            }
        } else {
            int u2 = u - 8192;
            int mt = u2 / 24, nt = u2 % 24;
            gemm_mma(emb + (size_t)mt * 64 * E_, E_,
                     W_ih + (size_t)nt * 128 * KA, KA,
                     g_gxe + (size_t)mt * 64 * G3 + nt * 128, G3, E_, 0, sm);
        }
    }
    phase_gate(3, &c_p8, 37u);   // phase-0 complete (c_p8 stream primed with 37)

    for (int t = 0; t < L_; t++) {
        const unsigned t1 = (unsigned)(t + 1);

        // ---- P1 (static): gx-h (u<192) + gh (u>=192), Kc=128 ----
        for (int u = bid; u < 384; u += NBLK) {
            if (u < 192) {
                int nt = u % 24, s = u / 24;
                gemm_mma(g_h + s * 128, H_,
                         W_ih + (size_t)nt * 128 * KA + E_ + s * 128, KA,
                         g_gxp + (size_t)s * B_ * G3 + nt * 128, G3, 128, 0, sm);
            } else {
                int u2 = u - 192;
                int nt = u2 % 24, s = u2 / 24;
                gemm_mma(g_h + s * 128, H_,
                         W_hh + (size_t)nt * 128 * H_ + s * 128, H_,
                         g_ghp + (size_t)s * B_ * G3 + nt * 128, G3, 128, 0, sm);
            }
        }
        phase_gate(0, &c_p1, 37u * t1);

        // ---- GRU (static, bids 0..255) ----
        {
            int i = bid * NTHR + tid;
            if (i < B_ * H_) {
                int b = i >> 10, j = i & 1023;
                const float* ge = &g_gxe[(size_t)(b * L_ + t) * G3];
                float gxr = ge[j], gxz = ge[H_ + j], gxn = ge[2 * H_ + j];
                float ghr = 0.f, ghz = 0.f, ghn = 0.f;
#pragma unroll
                for (int s = 0; s < S1; s++) {
                    const float* p = &g_gxp[((size_t)s * B_ + b) * G3];
                    gxr += __ldcg(p + j); gxz += __ldcg(p + H_ + j); gxn += __ldcg(p + 2 * H_ + j);
                }
#pragma unroll
                for (int s = 0; s < S1; s++) {
                    const float* p = &g_ghp[((size_t)s * B_ + b) * G3];
                    ghr += __ldcg(p + j); ghz += __ldcg(p + H_ + j); ghn += __ldcg(p + 2 * H_ + j);
                }
                float r = 1.f / (1.f + expf(-(gxr + b_ih[j]        + ghr + b_hh[j])));
                float z = 1.f / (1.f + expf(-(gxz + b_ih[H_ + j]   + ghz + b_hh[H_ + j])));
                float n = tanhf(gxn + b_ih[2 * H_ + j] + r * (ghn + b_hh[2 * H_ + j]));
                float h = __ldcg(&g_h[i]);
                g_xf[i] = (1.f - z) * n + z * h;
            }
        }
        phase_gate(1, &c_gru, 37u * t1);

        // ---- QF (static, bids 0..255): q (u<128) + final-rnn (u>=128), Kc=64 ----
        if (bid < 256) {
            if (bid < 128) {
                int s = bid >> 3, nt = bid & 7;
                gemm_mma(g_xf + s * 64, H_,
                         Wq + (size_t)nt * 128 * H_ + s * 64, H_,
                         g_qp + (size_t)s * B_ * H_ + nt * 128, H_, 64, 0, sm);
            } else {
                int u2 = bid - 128;
                int s = u2 >> 3, nt = u2 & 7;
                gemm_mma(g_xf + s * 64, H_,
                         Wm + (size_t)nt * 128 * 2 * H_ + s * 64, 2 * H_,
                         g_fp + (size_t)s * B_ * H_ + nt * 128, H_, 64, 0, sm);
            }
        }
        phase_gate(2, &c_qf, 37u * t1);

        // ---- SCORE+P8 fused (static, bids 0..255): (b, qtr) ----
        if (bid < 256) {
            int b = bid >> 2, qtr = bid & 3;
            // --- score quarter ---
            for (int j = tid; j < H_; j += NTHR) {
                float a = 0.f;
#pragma unroll
                for (int s = 0; s < SQ; s++)
                    a += __ldcg(&g_qp[((size_t)s * B_ + b) * H_ + j]);
                sm[j] = a;
                sm[H_ + j] = v_att[j];
            }
            __syncthreads();
            int w = tid >> 5, lane = tid & 31;
            for (int i = 0; i < 16; i++) {
                int n = qtr * 128 + w * 16 + i;
                const uint4* kp = (const uint4*)(g_keysb + (size_t)(b * N_ + n) * H_);
                float acc = 0.f;
#pragma unroll
                for (int j2 = 0; j2 < 4; j2++) {
                    uint4 kv = kp[lane + 32 * j2];
                    int c8 = (lane + 32 * j2) << 3;
                    float4 q0 = *(const float4*)(sm + c8);
                    float4 q1 = *(const float4*)(sm + c8 + 4);
                    float4 v0 = *(const float4*)(sm + H_ + c8);
                    float4 v1 = *(const float4*)(sm + H_ + c8 + 4);
                    acc += v0.x * tanh_fast(q0.x + __uint_as_float(kv.x << 16));
                    acc += v0.y * tanh_fast(q0.y + __uint_as_float(kv.x & 0xFFFF0000u));
                    acc += v0.z * tanh_fast(q0.z + __uint_as_float(kv.y << 16));
                    acc += v0.w * tanh_fast(q0.w + __uint_as_float(kv.y & 0xFFFF0000u));
                    acc += v1.x * tanh_fast(q1.x + __uint_as_float(kv.z << 16));
                    acc += v1.y * tanh_fast(q1.y + __uint_as_float(kv.z & 0xFFFF0000u));
                    acc += v1.z * tanh_fast(q1.z + __uint_as_float(kv.w << 16));
                    acc += v1.w * tanh_fast(q1.w + __uint_as_float(kv.w & 0xFFFF0000u));
                }
#pragma unroll
                for (int o = 16; o; o >>= 1) acc += __shfl_xor_sync(0xffffffffu, acc, o);
                if (lane == 0) {
                    float mk = vmask[b * N_ + n];
                    g_score[b * N_ + n] = (mk > 0.f) ? acc : -1e9f;
                }
            }
            __syncthreads();
            if (tid == 0) {
                __threadfence();
                unsigned old = atomicAdd(&g_bc[b], 1u);
                s_flag = ((old & 3u) == 3u) ? 1 : 0;
            }
            __syncthreads();
            if (s_flag) {
                // --- 4th finisher: softmax for b ---
                __threadfence();
                float s0 = __ldcg(&g_score[b * N_ + tid]);
                float s1 = __ldcg(&g_score[b * N_ + 256 + tid]);
                float m = fmaxf(s0, s1);
#pragma unroll
                for (int o = 16; o; o >>= 1) m = fmaxf(m, __shfl_xor_sync(0xffffffffu, m, o));
                if (lane == 0) red[w] = m;
                __syncthreads();
                float M = red[0];
#pragma unroll
                for (int i2 = 1; i2 < 8; i2++) M = fmaxf(M, red[i2]);
                float p0 = expf(s0 - M), p1 = expf(s1 - M);
                float ss = p0 + p1;
#pragma unroll
                for (int o = 16; o; o >>= 1) ss += __shfl_xor_sync(0xffffffffu, ss, o);
                if (lane == 0) red[8 + w] = ss;
                __syncthreads();
                float Z = red[8];
#pragma unroll
                for (int i2 = 1; i2 < 8; i2++) Z += red[8 + i2];
                float inv = 1.f / Z;
                float a0 = p0 * inv, a1 = p1 * inv;
                g_attn[b * N_ + tid] = a0;
                g_attn[b * N_ + 256 + tid] = a1;
                attn_out[((size_t)b * L_ + t) * N_ + tid] = a0;
                attn_out[((size_t)b * L_ + t) * N_ + 256 + tid] = a1;
                __syncthreads();
                if (tid == 0) {
                    __threadfence();
                    atomicAdd(&g_smb[b], 1u);
                }
            }
            // --- P8(b, qtr): wait for this b's softmax, then fused fc + tanh ---
            __syncthreads();
            if (tid == 0) {
                while ((int)(*(volatile unsigned*)&g_smb[b] - t1) < 0) __nanosleep(32);
            }
            __syncthreads();
            __threadfence();
            sm[tid] = __ldcg(&g_attn[b * N_ + tid]);
            sm[256 + tid] = __ldcg(&g_attn[b * N_ + 256 + tid]);
            __syncthreads();
            int nh = tid >> 7, pp = tid & 127;
            int pair = qtr * 128 + pp;
            const __nv_bfloat162* vp =
                (const __nv_bfloat162*)(g_vw + (size_t)b * N_ * H_) + pair;
            const float* aw = sm + nh * 256;
            vp += (size_t)(nh * 256) * (H_ / 2);
            float a0 = 0.f, a1 = 0.f;
#pragma unroll 8
            for (int n = 0; n < 256; n++) {
                float2 f = __bfloat1622float2(vp[(size_t)n * (H_ / 2)]);
                float wv = aw[n];
                a0 += wv * f.x;
                a1 += wv * f.y;
            }
            sm[512 + 2 * tid]     = a0;
            sm[512 + 2 * tid + 1] = a1;
            __syncthreads();
            if (tid < 128) {
                float f0 = sm[512 + 2 * tid] + sm[512 + 2 * (tid + 128)];
                float f1 = sm[512 + 2 * tid + 1] + sm[512 + 2 * (tid + 128) + 1];
                int h0 = 2 * (qtr * 128 + tid);
                float v0 = bm[h0] + f0;
                float v1 = bm[h0 + 1] + f1;
#pragma unroll
                for (int s = 0; s < SF; s++) {
                    float2 fp2 = __ldcg((const float2*)&g_fp[((size_t)s * B_ + b) * H_ + h0]);
                    v0 += fp2.x;
                    v1 += fp2.y;
                }
                float y0 = tanhf(v0), y1 = tanhf(v1);
                *(float2*)&out[((size_t)b * L_ + t) * H_ + h0] = make_float2(y0, y1);
                *(float2*)&g_h[b * H_ + h0] = make_float2(y0, y1);
            }
        }
        phase_gate(3, &c_p8, 37u * (unsigned)(t + 2));
    }

    // ---- end: last CTA resets all monotone state for next graph replay ----
    __syncthreads();
    if (tid == 0) {
        __threadfence();
        unsigned old = atomicAdd(&c_end, 1u);
        if (old == NBLK - 1u) {
            c_p1 = 0; c_gru = 0; c_qf = 0; c_p8 = 0;
            for (int i = 0; i < 4 * 37 * 32; i++) g_grp[i] = 0;
            for (int b = 0; b < B_; b++) { g_bc[b] = 0; g_smb[b] = 0; }
            __threadfence();
            atomicExch(&c_end, 0u);
        }
    }
}

// ---------------- launch: ONE graph node ----------------
extern "C" void kernel_launch(void* const* d_in, const int* in_sizes, int n_in,
                              void* d_out, int out_size) {
    const float* emb    = (const float*)d_in[0];
    const float* value  = (const float*)d_in[1];
    const float* vmask  = (const float*)d_in[2];
    const float* state  = (const float*)d_in[3];
    const float* W_ih   = (const float*)d_in[4];
    const float* b_ih   = (const float*)d_in[5];
    const float* W_hh   = (const float*)d_in[6];
    const float* b_hh   = (const float*)d_in[7];
    const float* Wq     = (const float*)d_in[8];
    const float* Wk     = (const float*)d_in[9];
    const float* v_att  = (const float*)d_in[10];
    const float* Wm     = (const float*)d_in[11];
    const float* bm     = (const float*)d_in[12];

    float* out      = (float*)d_out;                 // outputs: B x L x H
    float* attn_out = out + (size_t)B_ * L_ * H_;    // attns:   B x L x N

    decoder_all<<<NBLK, NTHR>>>(emb, value, vmask, state, W_ih, b_ih, W_hh, b_hh,
                                Wq, Wk, v_att, Wm, bm, out, attn_out);
}